// round 4
// baseline (speedup 1.0000x reference)
#include <cuda_runtime.h>

#define NMAX 512

// Scratch (device globals per allocation-free rule)
__device__ float g_D[NMAX * NMAX];  // pairwise distances, diag = 1e6
__device__ float g_prec[NMAX];      // per-query soft precision
__device__ int   g_ctr;             // arrival counter (zero-init; last block resets)

__device__ __forceinline__ float sigmoidf_(float x) {
    if (x >= 0.f) { float e = __expf(-x); return 1.f / (1.f + e); }
    else          { float e = __expf(x);  return e / (1.f + e); }
}

__device__ __forceinline__ float sig_sat(float x) {
    // |x|>18 -> 0/1 (err < 1.6e-8); most args here are O(100)
    if (x > 18.f)  return 1.f;
    if (x < -18.f) return 0.f;
    float e = __expf(-x);
    return 1.f / (1.f + e);
}

// ---------------- Kernel 1: fused Gram -> distance matrix ----------------
#define BM 32
#define BN 64
#define BK 32

__global__ void __launch_bounds__(256, 1) k_gram(const float* __restrict__ emb, int n, int dim) {
    __shared__ float sa[BK][BM + 2];
    __shared__ float sb[BK][BN];
    __shared__ float snA[BM];
    __shared__ float snB[BN];

    const int t  = threadIdx.x;
    const int tx = t & 15;
    const int ty = t >> 4;
    const int q0 = blockIdx.y * BM;
    const int m0 = blockIdx.x * BN;

    // Prologue: row norms for this block's 32 q-rows + 64 m-rows (warp-parallel,
    // deterministic order, redundant across blocks but trivial in cost)
    {
        const int w = t >> 5, l = t & 31;
        for (int rr = w; rr < BM + BN; rr += 8) {
            int row = (rr < BM) ? (q0 + rr) : (m0 + rr - BM);
            const float4* p = reinterpret_cast<const float4*>(emb + (size_t)row * dim);
            float s = 0.f;
            for (int i = l; i < dim / 4; i += 32) {
                float4 v = p[i];
                s = fmaf(v.x, v.x, fmaf(v.y, v.y, fmaf(v.z, v.z, fmaf(v.w, v.w, s))));
            }
#pragma unroll
            for (int o = 16; o; o >>= 1) s += __shfl_xor_sync(0xffffffffu, s, o);
            if (l == 0) { if (rr < BM) snA[rr] = s; else snB[rr - BM] = s; }
        }
    }
    __syncthreads();

    float acc[2][4] = {{0.f,0.f,0.f,0.f},{0.f,0.f,0.f,0.f}};

    for (int kt = 0; kt < dim; kt += BK) {
        {
            int r = t >> 3;
            int c = (t & 7) * 4;
            float4 v = *reinterpret_cast<const float4*>(&emb[(size_t)(q0 + r) * dim + kt + c]);
            sa[c + 0][r] = v.x; sa[c + 1][r] = v.y; sa[c + 2][r] = v.z; sa[c + 3][r] = v.w;
        }
        {
            int r = t >> 2;
            int c = (t & 3) * 8;
            const float* p = &emb[(size_t)(m0 + r) * dim + kt + c];
            float4 v0 = *reinterpret_cast<const float4*>(p);
            float4 v1 = *reinterpret_cast<const float4*>(p + 4);
            sb[c + 0][r] = v0.x; sb[c + 1][r] = v0.y; sb[c + 2][r] = v0.z; sb[c + 3][r] = v0.w;
            sb[c + 4][r] = v1.x; sb[c + 5][r] = v1.y; sb[c + 6][r] = v1.z; sb[c + 7][r] = v1.w;
        }
        __syncthreads();
#pragma unroll
        for (int k = 0; k < BK; k++) {
            float a0 = sa[k][ty * 2 + 0];
            float a1 = sa[k][ty * 2 + 1];
            float4 bv = *reinterpret_cast<const float4*>(&sb[k][tx * 4]);
            acc[0][0] = fmaf(a0, bv.x, acc[0][0]);
            acc[0][1] = fmaf(a0, bv.y, acc[0][1]);
            acc[0][2] = fmaf(a0, bv.z, acc[0][2]);
            acc[0][3] = fmaf(a0, bv.w, acc[0][3]);
            acc[1][0] = fmaf(a1, bv.x, acc[1][0]);
            acc[1][1] = fmaf(a1, bv.y, acc[1][1]);
            acc[1][2] = fmaf(a1, bv.z, acc[1][2]);
            acc[1][3] = fmaf(a1, bv.w, acc[1][3]);
        }
        __syncthreads();
    }

    // Epilogue: write final distances (diag = 1e6)
#pragma unroll
    for (int i = 0; i < 2; i++) {
        int q = q0 + ty * 2 + i;
        int m = m0 + tx * 4;
        float nq = snA[ty * 2 + i];
        float dv[4];
#pragma unroll
        for (int c = 0; c < 4; c++) {
            float d2 = nq + snB[tx * 4 + c] - 2.f * acc[i][c];
            dv[c] = (q == m + c) ? 1e6f : sqrtf(fmaxf(d2, 1e-12f));
        }
        *reinterpret_cast<float4*>(&g_D[(size_t)q * n + m]) =
            make_float4(dv[0], dv[1], dv[2], dv[3]);
    }
}

// ---------------- Kernel 2: warp-per-query soft precision ----------------
// 128 blocks x 128 threads = 512 warps: one warp per query, one block barrier.
__global__ void __launch_bounds__(128) k_prec(const int* __restrict__ labels,
                                              float* __restrict__ out,
                                              int n, float Kf) {
    __shared__ float sd[4][NMAX];   // per-warp distance row
    __shared__ int   slab[NMAX];    // labels (block-shared)
    __shared__ float sdj[4][64];    // per-warp gt distances (ascending j)
    __shared__ float bsum[4];
    __shared__ int   s_last;

    const int tid  = threadIdx.x;
    const int lane = tid & 31;
    const int w    = tid >> 5;
    const int q    = blockIdx.x * 4 + w;

    // labels -> smem (coalesced, 1 int4/thread)
    reinterpret_cast<int4*>(slab)[tid] = reinterpret_cast<const int4*>(labels)[tid];

    // own distance row -> smem (4 float4/lane)
    const float4* rp = reinterpret_cast<const float4*>(g_D + (size_t)q * NMAX);
#pragma unroll
    for (int i = 0; i < 4; i++)
        reinterpret_cast<float4*>(sd[w])[lane + 32 * i] = rp[lane + 32 * i];
    __syncthreads();

    // in-warp gt compaction on smem labels (ascending j => deterministic)
    const int lq = slab[q];
    int cnt = 0;
#pragma unroll
    for (int base = 0; base < NMAX; base += 32) {
        int j = base + lane;
        bool f = (j != q) && (slab[j] == lq);
        unsigned b = __ballot_sync(0xffffffffu, f);
        int pos = cnt + __popc(b & ((1u << lane) - 1u));
        if (f && pos < 64) sdj[w][pos] = sd[w][j];
        cnt += __popc(b);
    }
    const int gtc = (cnt < 64) ? cnt : 64;
    __syncwarp();

    // soft rank per gt; all lanes accumulate num identically (deterministic order)
    float num = 0.f;
    for (int g = 0; g < gtc; g++) {
        float dj = sdj[w][g];
        float part = 0.f;
#pragma unroll 4
        for (int m = lane; m < NMAX; m += 32)
            part += sig_sat((dj - sd[w][m]) * 100.0f);   // 1/T2
#pragma unroll
        for (int o = 16; o; o >>= 1)
            part += __shfl_xor_sync(0xffffffffu, part, o);
        num += sigmoidf_(Kf - part);                     // T1 = 1
    }
    if (lane == 0)
        g_prec[q] = num / fminf((float)gtc, Kf);         // 0/0 -> NaN like reference

    __syncthreads();
    if (tid == 0) {
        __threadfence();
        int old = atomicAdd(&g_ctr, 1);
        s_last = (old == gridDim.x - 1) ? 1 : 0;
    }
    __syncthreads();

    if (s_last) {
        __threadfence();
        float v = 0.f;
        for (int i = tid; i < NMAX; i += 128) v += g_prec[i];
#pragma unroll
        for (int o = 16; o; o >>= 1)
            v += __shfl_xor_sync(0xffffffffu, v, o);
        if (lane == 0) bsum[w] = v;
        __syncthreads();
        if (tid == 0) {
            out[0] = 1.0f - (bsum[0] + bsum[1] + bsum[2] + bsum[3]) / (float)NMAX;
            g_ctr = 0;   // reset for next graph replay
        }
    }
}

extern "C" void kernel_launch(void* const* d_in, const int* in_sizes, int n_in,
                              void* d_out, int out_size) {
    const float* emb    = (const float*)d_in[0];
    const int*   labels = (const int*)d_in[1];
    const int n   = in_sizes[1];        // 512
    const int dim = in_sizes[0] / n;    // 384

    dim3 gd(n / BN, n / BM);            // 128 blocks
    k_gram<<<gd, 256>>>(emb, n, dim);
    k_prec<<<n / 4, 128>>>(labels, (float*)d_out, n, 5.0f);
}

// round 5
// speedup vs baseline: 1.8719x; 1.8719x over previous
#include <cuda_runtime.h>

#define NMAX 512

// Scratch (device globals per allocation-free rule)
__device__ float g_D[NMAX * NMAX];  // pairwise distances, diag = 1e6
__device__ float g_prec[NMAX];      // per-query soft precision
__device__ int   g_ctr;             // arrival counter (zero-init; last block resets)

__device__ __forceinline__ float sigmoidf_(float x) {
    if (x >= 0.f) { float e = __expf(-x); return 1.f / (1.f + e); }
    else          { float e = __expf(x);  return e / (1.f + e); }
}

__device__ __forceinline__ float sig_sat(float x) {
    // |x|>18 -> 0/1 (err < 1.6e-8); args here are mostly O(100)
    if (x > 18.f)  return 1.f;
    if (x < -18.f) return 0.f;
    float e = __expf(-x);
    return 1.f / (1.f + e);
}

// ---------------- Kernel 1: fused Gram -> distance matrix ----------------
// Norms accumulated in-register during tile loads (no prologue).
#define BM 32
#define BN 64
#define BK 32

__global__ void __launch_bounds__(256, 1) k_gram(const float* __restrict__ emb, int n, int dim) {
    __shared__ float sa[BK][BM + 2];
    __shared__ float sb[BK][BN];
    __shared__ float snA[BM];
    __shared__ float snB[BN];

    const int t  = threadIdx.x;
    const int tx = t & 15;
    const int ty = t >> 4;
    const int q0 = blockIdx.y * BM;
    const int m0 = blockIdx.x * BN;

    float acc[2][4] = {{0.f,0.f,0.f,0.f},{0.f,0.f,0.f,0.f}};
    float nA = 0.f;   // partial norm of A-row (t>>3), cols (t&7)*4..+3, all k-tiles
    float nB = 0.f;   // partial norm of B-row (t>>2), cols (t&3)*8..+7

    for (int kt = 0; kt < dim; kt += BK) {
        {
            int r = t >> 3;
            int c = (t & 7) * 4;
            float4 v = *reinterpret_cast<const float4*>(&emb[(size_t)(q0 + r) * dim + kt + c]);
            sa[c + 0][r] = v.x; sa[c + 1][r] = v.y; sa[c + 2][r] = v.z; sa[c + 3][r] = v.w;
            nA = fmaf(v.x, v.x, fmaf(v.y, v.y, fmaf(v.z, v.z, fmaf(v.w, v.w, nA))));
        }
        {
            int r = t >> 2;
            int c = (t & 3) * 8;
            const float* p = &emb[(size_t)(m0 + r) * dim + kt + c];
            float4 v0 = *reinterpret_cast<const float4*>(p);
            float4 v1 = *reinterpret_cast<const float4*>(p + 4);
            sb[c + 0][r] = v0.x; sb[c + 1][r] = v0.y; sb[c + 2][r] = v0.z; sb[c + 3][r] = v0.w;
            sb[c + 4][r] = v1.x; sb[c + 5][r] = v1.y; sb[c + 6][r] = v1.z; sb[c + 7][r] = v1.w;
            nB = fmaf(v0.x, v0.x, fmaf(v0.y, v0.y, fmaf(v0.z, v0.z, fmaf(v0.w, v0.w, nB))));
            nB = fmaf(v1.x, v1.x, fmaf(v1.y, v1.y, fmaf(v1.z, v1.z, fmaf(v1.w, v1.w, nB))));
        }
        __syncthreads();
#pragma unroll
        for (int k = 0; k < BK; k++) {
            float a0 = sa[k][ty * 2 + 0];
            float a1 = sa[k][ty * 2 + 1];
            float4 bv = *reinterpret_cast<const float4*>(&sb[k][tx * 4]);
            acc[0][0] = fmaf(a0, bv.x, acc[0][0]);
            acc[0][1] = fmaf(a0, bv.y, acc[0][1]);
            acc[0][2] = fmaf(a0, bv.z, acc[0][2]);
            acc[0][3] = fmaf(a0, bv.w, acc[0][3]);
            acc[1][0] = fmaf(a1, bv.x, acc[1][0]);
            acc[1][1] = fmaf(a1, bv.y, acc[1][1]);
            acc[1][2] = fmaf(a1, bv.z, acc[1][2]);
            acc[1][3] = fmaf(a1, bv.w, acc[1][3]);
        }
        __syncthreads();
    }

    // finish norms: reduce within the lane-groups that share a row
    nA += __shfl_xor_sync(0xffffffffu, nA, 1);
    nA += __shfl_xor_sync(0xffffffffu, nA, 2);
    nA += __shfl_xor_sync(0xffffffffu, nA, 4);
    if ((t & 7) == 0) snA[t >> 3] = nA;
    nB += __shfl_xor_sync(0xffffffffu, nB, 1);
    nB += __shfl_xor_sync(0xffffffffu, nB, 2);
    if ((t & 3) == 0) snB[t >> 2] = nB;
    __syncthreads();

    // Epilogue: final distances (diag = 1e6)
#pragma unroll
    for (int i = 0; i < 2; i++) {
        int q = q0 + ty * 2 + i;
        int m = m0 + tx * 4;
        float nq = snA[ty * 2 + i];
        float dv[4];
#pragma unroll
        for (int c = 0; c < 4; c++) {
            float d2 = nq + snB[tx * 4 + c] - 2.f * acc[i][c];
            dv[c] = (q == m + c) ? 1e6f : sqrtf(fmaxf(d2, 1e-12f));
        }
        *reinterpret_cast<float4*>(&g_D[(size_t)q * n + m]) =
            make_float4(dv[0], dv[1], dv[2], dv[3]);
    }
}

// ---------------- Kernel 2: block-per-query, warp-owns-j-range ----------------
// 512 blocks x 256 threads. No compaction pass: warp w handles j in
// [w*64, (w+1)*64) found via two smem ballots. Two block barriers total.
__global__ void __launch_bounds__(256) k_prec(const int* __restrict__ labels,
                                              float* __restrict__ out, float Kf) {
    __shared__ float sd[NMAX];
    __shared__ int   slab[NMAX];
    __shared__ float swnum[8];
    __shared__ int   swcnt[8];
    __shared__ float bsum[8];
    __shared__ int   s_last;

    const int q    = blockIdx.x;
    const int tid  = threadIdx.x;
    const int lane = tid & 31;
    const int w    = tid >> 5;

    // coalesced loads: 2 ints + 2 floats per thread
    reinterpret_cast<int2*>(slab)[tid] = reinterpret_cast<const int2*>(labels)[tid];
    reinterpret_cast<float2*>(sd)[tid] =
        reinterpret_cast<const float2*>(g_D + (size_t)q * NMAX)[tid];
    __syncthreads();

    const int lq = slab[q];
    const int base = w * 64;
    const int j0 = base + lane, j1 = j0 + 32;
    const bool f0 = (j0 != q) && (slab[j0] == lq);
    const bool f1 = (j1 != q) && (slab[j1] == lq);
    unsigned b0 = __ballot_sync(0xffffffffu, f0);
    unsigned b1 = __ballot_sync(0xffffffffu, f1);
    const int cnt = __popc(b0) + __popc(b1);

    float num = 0.f;
#pragma unroll
    for (int half = 0; half < 2; half++) {
        unsigned mm = half ? b1 : b0;
        int hb = base + half * 32;
        while (mm) {                       // ascending j: deterministic
            int bit = __ffs(mm) - 1;
            mm &= mm - 1;
            float dj = sd[hb + bit];
            float part = 0.f;
#pragma unroll 4
            for (int m = lane; m < NMAX; m += 32)
                part += sig_sat((dj - sd[m]) * 100.0f);   // 1/T2
#pragma unroll
            for (int o = 16; o; o >>= 1)
                part += __shfl_xor_sync(0xffffffffu, part, o);
            num += sigmoidf_(Kf - part);                  // T1 = 1
        }
    }
    if (lane == 0) { swnum[w] = num; swcnt[w] = cnt; }
    __syncthreads();

    if (tid == 0) {
        float s = 0.f; int gtc = 0;
#pragma unroll
        for (int i = 0; i < 8; i++) { s += swnum[i]; gtc += swcnt[i]; }
        g_prec[q] = s / fminf((float)gtc, Kf);   // 0/0 -> NaN matches reference
        __threadfence();
        int old = atomicAdd(&g_ctr, 1);
        s_last = (old == gridDim.x - 1) ? 1 : 0;
    }
    __syncthreads();

    if (s_last) {
        __threadfence();
        float v = 0.f;
        for (int i = tid; i < NMAX; i += 256) v += g_prec[i];
#pragma unroll
        for (int o = 16; o; o >>= 1)
            v += __shfl_xor_sync(0xffffffffu, v, o);
        if (lane == 0) bsum[w] = v;
        __syncthreads();
        if (tid == 0) {
            float s = 0.f;
#pragma unroll
            for (int i = 0; i < 8; i++) s += bsum[i];
            out[0] = 1.0f - s / (float)NMAX;
            g_ctr = 0;   // reset for next graph replay
        }
    }
}

extern "C" void kernel_launch(void* const* d_in, const int* in_sizes, int n_in,
                              void* d_out, int out_size) {
    const float* emb    = (const float*)d_in[0];
    const int*   labels = (const int*)d_in[1];
    const int n   = in_sizes[1];        // 512
    const int dim = in_sizes[0] / n;    // 384

    dim3 gd(n / BN, n / BM);            // 128 blocks
    k_gram<<<gd, 256>>>(emb, n, dim);
    k_prec<<<n, 256>>>(labels, (float*)d_out, 5.0f);
}